// round 5
// baseline (speedup 1.0000x reference)
#include <cuda_runtime.h>

// Reference semantics reduce to (softmax over a size-1 axis == 1; W is dead code):
//   out[i, 0:512]    = 2*X[i]                              for i < 64
//   out[i, 0:512]    = X[i] + sum_{r=i-64..i-1} X[r]       for i >= 64
//   out[i, 512:1024] = X[i]
//
// Two-pass: K1 builds 8-row chunk sums (and does the rows-0..63 copy, which has
// no dependency); K2 warms each 8-row strip's 64-row window from 8 aligned
// chunk sums and runs a short sliding loop with all loads hoisted (needs the
// big register budget from __launch_bounds__(128, 1)).

#define NROWS  4096
#define DCOLS  512
#define LENS   64
#define CHUNK  8                 // rows per chunk (and per strip)
#define NCHUNK (NROWS / CHUNK)   // 512
#define D4     (DCOLS / 4)       // 128 float4 per row
#define OD4    (2 * D4)          // 256 float4 per output row
#define NCOPYBLK (LENS / CHUNK)  // 8 blocks for rows 0..63
#define NSTRIP ((NROWS - LENS) / CHUNK)  // 504

// Scratch: chunk sums, 512 chunks x 128 float4 = 1 MB
__device__ float4 g_chunk[NCHUNK * D4];

static __device__ __forceinline__ float4 f4add(float4 a, float4 b) {
    return make_float4(a.x + b.x, a.y + b.y, a.z + b.z, a.w + b.w);
}

// K1: chunk sums (blocks 0..511) + rows 0..63 copy (blocks 512..519)
__global__ __launch_bounds__(128, 1) void chunk_sum_kernel(
    const float4* __restrict__ X4, float4* __restrict__ O4)
{
    const int c = threadIdx.x;       // float4 column
    const int k = blockIdx.x;

    if (k < NCHUNK) {
        const float4* p = X4 + (size_t)(k * CHUNK) * D4 + c;
        float4 x[CHUNK];
        #pragma unroll
        for (int j = 0; j < CHUNK; ++j) x[j] = p[(size_t)j * D4];
        // tree reduction
        float4 s01 = f4add(x[0], x[1]);
        float4 s23 = f4add(x[2], x[3]);
        float4 s45 = f4add(x[4], x[5]);
        float4 s67 = f4add(x[6], x[7]);
        g_chunk[k * D4 + c] = f4add(f4add(s01, s23), f4add(s45, s67));
    } else {
        // rows 0..63: left = 2X, right = X
        const int i0 = (k - NCHUNK) * CHUNK;
        #pragma unroll
        for (int r = 0; r < CHUNK; ++r) {
            const int i = i0 + r;
            float4 x = X4[(size_t)i * D4 + c];
            float4 h = make_float4(2.f * x.x, 2.f * x.y, 2.f * x.z, 2.f * x.w);
            O4[(size_t)i * OD4 + c]      = h;
            O4[(size_t)i * OD4 + D4 + c] = x;
        }
    }
}

// K2: strip s covers output rows [64+8s, 64+8s+8). Window [8s, 8s+64) = chunks s..s+7.
__global__ __launch_bounds__(128, 1) void slide_out_kernel(
    const float4* __restrict__ X4, float4* __restrict__ O4)
{
    const int c = threadIdx.x;
    const int s = blockIdx.x;               // 0..503
    const int i0 = LENS + s * CHUNK;

    // Issue ALL loads up front (24 independent LDG.128 -> high MLP).
    float4 cs[CHUNK], xi[CHUNK], xm[CHUNK];
    const float4* gp = g_chunk + (size_t)s * D4 + c;
    #pragma unroll
    for (int j = 0; j < CHUNK; ++j) cs[j] = gp[(size_t)j * D4];
    const float4* pi = X4 + (size_t)i0 * D4 + c;
    const float4* pm = X4 + (size_t)(i0 - LENS) * D4 + c;
    #pragma unroll
    for (int r = 0; r < CHUNK; ++r) {
        xi[r] = pi[(size_t)r * D4];
        xm[r] = pm[(size_t)r * D4];
    }

    // Right-half copy stores depend only on xi — issue them immediately.
    float4* po = O4 + (size_t)i0 * OD4 + c;
    #pragma unroll
    for (int r = 0; r < CHUNK; ++r)
        po[(size_t)r * OD4 + D4] = xi[r];

    // Warm-up window sum: tree over the 8 chunk sums.
    float4 w = f4add(f4add(f4add(cs[0], cs[1]), f4add(cs[2], cs[3])),
                     f4add(f4add(cs[4], cs[5]), f4add(cs[6], cs[7])));

    // Precompute per-row deltas (independent FADDs) before the serial chain.
    float4 d[CHUNK];
    #pragma unroll
    for (int r = 0; r < CHUNK; ++r) {
        d[r] = make_float4(xi[r].x - xm[r].x, xi[r].y - xm[r].y,
                           xi[r].z - xm[r].z, xi[r].w - xm[r].w);
    }

    #pragma unroll
    for (int r = 0; r < CHUNK; ++r) {
        po[(size_t)r * OD4] = f4add(xi[r], w);
        w = f4add(w, d[r]);
    }
}

extern "C" void kernel_launch(void* const* d_in, const int* in_sizes, int n_in,
                              void* d_out, int out_size)
{
    const float4* X4 = (const float4*)d_in[0];   // X: (4096, 512) f32
    float4* O4 = (float4*)d_out;                 // out: (4096, 1024) f32

    chunk_sum_kernel<<<NCHUNK + NCOPYBLK, 128>>>(X4, O4);
    slide_out_kernel<<<NSTRIP, 128>>>(X4, O4);
}

// round 6
// speedup vs baseline: 1.0269x; 1.0269x over previous
#include <cuda_runtime.h>

// Reference semantics reduce to (softmax over a size-1 axis == 1; W is dead code):
//   out[i, 0:512]    = 2*X[i]                              for i < 64
//   out[i, 0:512]    = X[i] + sum_{r=i-64..i-1} X[r]       for i >= 64
//   out[i, 512:1024] = X[i]
//
// Prefix decomposition with chunk = LENS = 64:
//   PL[i] = intra-chunk inclusive row prefix,  T[k] = chunk-k total
//   W[i]  = PL[i-1] - PL[i-65] + T[(i-65)>>6]   (i >= 65)
//   W[64] = PL[63]
// -> K2 has NO serial chains: 4 independent loads + 2 stores per row.

#define NROWS 4096
#define DCOLS 512
#define LENS  64
#define D4    (DCOLS / 4)     // 128 float4 per input row
#define OD4   (2 * D4)        // 256 float4 per output row
#define NCH   (NROWS / LENS)  // 64 chunks
#define SEG   16              // rows per scan segment
#define NSEG  (LENS / SEG)    // 4 segments per chunk

// Scratch: intra-chunk prefixes (8 MB) + chunk totals (32 KB)
__device__ float4 g_PL[NROWS * D4];
__device__ float4 g_T[NCH * D4];

static __device__ __forceinline__ float4 f4add(float4 a, float4 b) {
    return make_float4(a.x + b.x, a.y + b.y, a.z + b.z, a.w + b.w);
}
static __device__ __forceinline__ float4 f4sub(float4 a, float4 b) {
    return make_float4(a.x - b.x, a.y - b.y, a.z - b.z, a.w - b.w);
}

// K1: blocks 0..255  -> segmented prefix scan (chunk k, column group g)
//     blocks 256..271 -> rows 0..63 copy (left = 2X, right = X)
__global__ __launch_bounds__(128, 1) void prefix_kernel(
    const float4* __restrict__ X4, float4* __restrict__ O4)
{
    const int b = blockIdx.x;

    if (b >= NCH * 4) {
        // copy blocks: 16 blocks x 4 rows
        const int i0 = (b - NCH * 4) * 4;
        const int c  = threadIdx.x;   // f4 column 0..127
        #pragma unroll
        for (int r = 0; r < 4; ++r) {
            const int i = i0 + r;
            float4 x = X4[(size_t)i * D4 + c];
            O4[(size_t)i * OD4 + c]      = f4add(x, x);
            O4[(size_t)i * OD4 + D4 + c] = x;
        }
        return;
    }

    // scan block: chunk k, column group g (32 f4 columns)
    const int k = b >> 2;
    const int g = b & 3;
    const int lane = threadIdx.x & 31;   // column within group
    const int s    = threadIdx.x >> 5;   // segment 0..3
    const int c    = g * 32 + lane;      // f4 column

    const int row0 = k * LENS + s * SEG;
    const float4* px = X4 + (size_t)row0 * D4 + c;

    float4 v[SEG];
    #pragma unroll
    for (int r = 0; r < SEG; ++r) v[r] = px[(size_t)r * D4];
    #pragma unroll
    for (int r = 1; r < SEG; ++r) v[r] = f4add(v[r], v[r - 1]);

    __shared__ float4 stot[NSEG][32];
    stot[s][lane] = v[SEG - 1];
    __syncthreads();

    float4 off = make_float4(0.f, 0.f, 0.f, 0.f);
    if (s > 0) off = f4add(off, stot[0][lane]);
    if (s > 1) off = f4add(off, stot[1][lane]);
    if (s > 2) off = f4add(off, stot[2][lane]);

    float4* ppl = g_PL + (size_t)row0 * D4 + c;
    #pragma unroll
    for (int r = 0; r < SEG; ++r) ppl[(size_t)r * D4] = f4add(v[r], off);

    if (s == NSEG - 1)
        g_T[(size_t)k * D4 + c] = f4add(v[SEG - 1], off);
}

// K2: block b handles output rows 64+4b .. 64+4b+3, fully parallel.
__global__ __launch_bounds__(128, 1) void window_out_kernel(
    const float4* __restrict__ X4, float4* __restrict__ O4)
{
    const int c  = threadIdx.x;
    const int i0 = LENS + 4 * blockIdx.x;

    float4 x[4], pl1[4], pl2[4], tt[4];
    const float4 zero = make_float4(0.f, 0.f, 0.f, 0.f);

    #pragma unroll
    for (int r = 0; r < 4; ++r) {
        const int i    = i0 + r;
        const int idx1 = i - 1;
        const int idx2 = i - 65;
        x[r]   = X4[(size_t)i * D4 + c];
        pl1[r] = g_PL[(size_t)idx1 * D4 + c];
        if (idx2 >= 0) {
            pl2[r] = g_PL[(size_t)idx2 * D4 + c];
            tt[r]  = g_T[(size_t)(idx2 >> 6) * D4 + c];
        } else {           // only row 64
            pl2[r] = zero;
            tt[r]  = zero;
        }
    }

    #pragma unroll
    for (int r = 0; r < 4; ++r) {
        const int i = i0 + r;
        float4 w = f4add(f4sub(pl1[r], pl2[r]), tt[r]);
        O4[(size_t)i * OD4 + c]      = f4add(x[r], w);
        O4[(size_t)i * OD4 + D4 + c] = x[r];
    }
}

extern "C" void kernel_launch(void* const* d_in, const int* in_sizes, int n_in,
                              void* d_out, int out_size)
{
    const float4* X4 = (const float4*)d_in[0];   // X: (4096, 512) f32
    float4* O4 = (float4*)d_out;                 // out: (4096, 1024) f32

    prefix_kernel<<<NCH * 4 + LENS / 4, 128>>>(X4, O4);          // 272 blocks
    window_out_kernel<<<(NROWS - LENS) / 4, 128>>>(X4, O4);      // 1008 blocks
}